// round 5
// baseline (speedup 1.0000x reference)
#include <cuda_runtime.h>
#include <cuda_bf16.h>
#include <math.h>

#define N_NODES 50000
#define N_EDGES 800000
#define D_IN    128
#define D_HID   256
#define N_CLS   16
#define N_PROT  512

// ---------------- scratch (device globals; no allocs allowed) ----------------
__device__ float g_dis[N_NODES];
__device__ int   g_indeg[N_NODES];
__device__ int   g_cursor[N_NODES];
__device__ int   g_rowptr[N_NODES + 1];
__device__ int   g_csr_src[N_EDGES];
__device__ float g_xw[(size_t)N_NODES * D_HID];       // GEMM output (pre-aggregation)
__device__ float g_h [(size_t)N_NODES * D_HID];       // hidden activations
__device__ float g_xrel_scratch[(size_t)N_NODES * N_PROT];  // fallback x_rel storage
__device__ float g_anchors [(size_t)N_PROT * D_HID];  // [P, H]
__device__ float g_anchorT [(size_t)D_HID * N_PROT];  // [H, P]
__device__ float g_outproto[(size_t)N_PROT * N_CLS];

// ---------------- graph prep ----------------
__global__ void k_zero_counts() {
    int i = blockIdx.x * blockDim.x + threadIdx.x;
    if (i < N_NODES) { g_indeg[i] = 0; g_cursor[i] = 0; }
}

// edge_index / prot are INT32: jnp.int64 degrades to int32 with JAX x64 disabled.
__global__ void k_count_deg(const int* __restrict__ dst) {
    int e = blockIdx.x * blockDim.x + threadIdx.x;
    if (e < N_EDGES) {
        int d = dst[e];
        if (d >= 0 && d < N_NODES) atomicAdd(&g_indeg[d], 1);
    }
}

__global__ void k_dis() {
    int i = blockIdx.x * blockDim.x + threadIdx.x;
    if (i < N_NODES) {
        float deg = (float)(g_indeg[i] + 1);  // +1 self loop
        g_dis[i] = 1.0f / sqrtf(deg);
    }
}

// single-block inclusive scan over in-degrees -> rowptr
__global__ void k_scan() {
    __shared__ int sh[1024];
    __shared__ int s_carry;
    int t = threadIdx.x;
    if (t == 0) { s_carry = 0; g_rowptr[0] = 0; }
    __syncthreads();
    for (int base = 0; base < N_NODES; base += 1024) {
        int i = base + t;
        int v = (i < N_NODES) ? g_indeg[i] : 0;
        sh[t] = v;
        __syncthreads();
        for (int off = 1; off < 1024; off <<= 1) {
            int u = (t >= off) ? sh[t - off] : 0;
            __syncthreads();
            sh[t] += u;
            __syncthreads();
        }
        if (i < N_NODES) g_rowptr[i + 1] = sh[t] + s_carry;
        __syncthreads();
        if (t == 0) s_carry += sh[1023];
        __syncthreads();
    }
}

__global__ void k_fill_csr(const int* __restrict__ src,
                           const int* __restrict__ dst) {
    int e = blockIdx.x * blockDim.x + threadIdx.x;
    if (e < N_EDGES) {
        int d = dst[e];
        int s = src[e];
        if (d < 0 || d >= N_NODES) return;
        int pos = atomicAdd(&g_cursor[d], 1);
        int idx = g_rowptr[d] + pos;
        if (idx >= 0 && idx < N_EDGES)
            g_csr_src[idx] = s;
    }
}

// ---------------- fp32 tiled GEMM body: C[M,N] = A[M,K] @ B[K,N] -------------
__device__ __forceinline__ void gemm_body(const float* __restrict__ A,
                                          const float* __restrict__ B,
                                          float* __restrict__ C,
                                          int M, int N, int K) {
    __shared__ float As[16][64];
    __shared__ float Bs[16][64];
    int bm = blockIdx.y * 64;
    int bn = blockIdx.x * 64;
    int t = threadIdx.x;
    int tx = t % 16, ty = t / 16;

    float acc[4][4];
#pragma unroll
    for (int r = 0; r < 4; r++)
#pragma unroll
        for (int c = 0; c < 4; c++) acc[r][c] = 0.0f;

    for (int k0 = 0; k0 < K; k0 += 16) {
        // load A tile (64 rows x 16 cols), one float4 per thread
        {
            int m = t >> 2;          // 0..63
            int kq = t & 3;          // 0..3
            float4 v = make_float4(0.f, 0.f, 0.f, 0.f);
            if (bm + m < M)
                v = *(const float4*)&A[(size_t)(bm + m) * K + k0 + kq * 4];
            As[kq * 4 + 0][m] = v.x;
            As[kq * 4 + 1][m] = v.y;
            As[kq * 4 + 2][m] = v.z;
            As[kq * 4 + 3][m] = v.w;
        }
        // load B tile (16 rows x 64 cols), one float4 per thread
        {
            int kk = t >> 4;         // 0..15
            int nq = t & 15;         // 0..15
            float4 v = *(const float4*)&B[(size_t)(k0 + kk) * N + bn + nq * 4];
            Bs[kk][nq * 4 + 0] = v.x;
            Bs[kk][nq * 4 + 1] = v.y;
            Bs[kk][nq * 4 + 2] = v.z;
            Bs[kk][nq * 4 + 3] = v.w;
        }
        __syncthreads();
#pragma unroll
        for (int kk = 0; kk < 16; kk++) {
            float av[4], bv[4];
#pragma unroll
            for (int r = 0; r < 4; r++) av[r] = As[kk][ty * 4 + r];
#pragma unroll
            for (int c = 0; c < 4; c++) bv[c] = Bs[kk][tx * 4 + c];
#pragma unroll
            for (int r = 0; r < 4; r++)
#pragma unroll
                for (int c = 0; c < 4; c++) acc[r][c] += av[r] * bv[c];
        }
        __syncthreads();
    }
#pragma unroll
    for (int r = 0; r < 4; r++) {
        int m = bm + ty * 4 + r;
        if (m < M) {
            float4 v = make_float4(acc[r][0], acc[r][1], acc[r][2], acc[r][3]);
            *(float4*)&C[(size_t)m * N + bn + tx * 4] = v;
        }
    }
}

// bindings (scratch buffers referenced directly as device globals)
__global__ void k_gemm_xw0(const float* __restrict__ x, const float* __restrict__ W0) {
    gemm_body(x, W0, g_xw, N_NODES, D_HID, D_IN);
}
__global__ void k_gemm_hw1(const float* __restrict__ W1) {
    gemm_body(g_h, W1, g_xw, N_NODES, D_HID, D_HID);
}
__global__ void k_gemm_xrel(float* __restrict__ xrel) {
    gemm_body(g_h, g_anchorT, xrel, N_NODES, N_PROT, D_HID);
}
__global__ void k_gemm_xrel_scratch() {
    gemm_body(g_h, g_anchorT, g_xrel_scratch, N_NODES, N_PROT, D_HID);
}

// ---------------- GCN aggregation (CSR gather, deterministic writes) ---------
__global__ void k_aggregate(const float* __restrict__ bias, int do_relu) {
    int node = blockIdx.x;
    int t = threadIdx.x;  // 64 threads, float4 each -> 256 cols
    float din = g_dis[node];
    int beg = g_rowptr[node], end = g_rowptr[node + 1];
    const float4* xw4 = (const float4*)g_xw;
    float4 acc = make_float4(0.f, 0.f, 0.f, 0.f);
    for (int e = beg; e < end; e++) {
        int s = g_csr_src[e];
        float w = g_dis[s] * din;
        float4 v = xw4[(size_t)s * 64 + t];
        acc.x += w * v.x; acc.y += w * v.y; acc.z += w * v.z; acc.w += w * v.w;
    }
    { // self loop
        float w = din * din;
        float4 v = xw4[(size_t)node * 64 + t];
        acc.x += w * v.x; acc.y += w * v.y; acc.z += w * v.z; acc.w += w * v.w;
    }
    float4 bv = ((const float4*)bias)[t];
    acc.x += bv.x; acc.y += bv.y; acc.z += bv.z; acc.w += bv.w;
    if (do_relu) {
        acc.x = fmaxf(acc.x, 0.f); acc.y = fmaxf(acc.y, 0.f);
        acc.z = fmaxf(acc.z, 0.f); acc.w = fmaxf(acc.w, 0.f);
    }
    ((float4*)g_h)[(size_t)node * 64 + t] = acc;
}

// ---------------- L2 row-normalize g_h in place ------------------------------
__global__ void k_rownorm() {
    int node = blockIdx.x;
    int t = threadIdx.x;  // 64
    float4* row = (float4*)(g_h + (size_t)node * D_HID);
    float4 v = row[t];
    float s = v.x * v.x + v.y * v.y + v.z * v.z + v.w * v.w;
#pragma unroll
    for (int off = 16; off >= 1; off >>= 1)
        s += __shfl_xor_sync(0xFFFFFFFFu, s, off);
    __shared__ float ws[2];
    if ((t & 31) == 0) ws[t >> 5] = s;
    __syncthreads();
    s = ws[0] + ws[1];
    float r = 1.0f / sqrtf(s);
    v.x *= r; v.y *= r; v.z *= r; v.w *= r;
    row[t] = v;
}

// ---------------- anchor gather (rows + transposed) --------------------------
__global__ void k_gather_anchors(const int* __restrict__ prot) {
    int p = blockIdx.x;
    int t = threadIdx.x;  // 256
    int nl = prot[p];
    int node = (nl >= 0 && nl < N_NODES) ? nl : 0;
    float v = g_h[(size_t)node * D_HID + t];
    g_anchors[(size_t)p * D_HID + t] = v;
    g_anchorT[(size_t)t * N_PROT + p] = v;
}

// ---------------- prototype head: log_softmax(lin(anchors)) ------------------
__global__ void k_proto_head(const float* __restrict__ Wl1, const float* __restrict__ bl1,
                             const float* __restrict__ Wl2, const float* __restrict__ bl2,
                             float* __restrict__ out_proto_dst, int write_out) {
    int p = blockIdx.x;
    int t = threadIdx.x;  // 256
    __shared__ float a[D_HID];
    __shared__ float h1[D_HID];
    __shared__ float z[N_CLS];
    a[t] = g_anchors[(size_t)p * D_HID + t];
    __syncthreads();
    float s = bl1[t];
#pragma unroll 4
    for (int k = 0; k < D_HID; k++) s += a[k] * Wl1[(size_t)k * D_HID + t];
    h1[t] = fmaxf(s, 0.0f);
    __syncthreads();
    if (t < N_CLS) {
        float s2 = bl2[t];
#pragma unroll 4
        for (int k = 0; k < D_HID; k++) s2 += h1[k] * Wl2[(size_t)k * N_CLS + t];
        z[t] = s2;
    }
    __syncthreads();
    if (t < N_CLS) {
        float m = z[0];
#pragma unroll
        for (int j = 1; j < N_CLS; j++) m = fmaxf(m, z[j]);
        float se = 0.f;
#pragma unroll
        for (int j = 0; j < N_CLS; j++) se += expf(z[j] - m);
        float v = z[t] - m - logf(se);
        g_outproto[(size_t)p * N_CLS + t] = v;
        if (write_out) out_proto_dst[(size_t)p * N_CLS + t] = v;
    }
}

// ---------------- out = log_softmax(x_rel @ out_proto) -----------------------
// 128 threads = 8 nodes x 16 classes per block
__device__ __forceinline__ void out_head_body(const float* __restrict__ xr_base,
                                              float* __restrict__ out) {
    __shared__ float ps[N_PROT * N_CLS];  // 32KB
    __shared__ float z[8][N_CLS];
    int t = threadIdx.x;
    for (int i = t; i < N_PROT * N_CLS; i += 128) ps[i] = g_outproto[i];
    __syncthreads();
    int g = t >> 4;          // node within block
    int c = t & 15;          // class
    int node = blockIdx.x * 8 + g;
    const float* xr = xr_base + (size_t)node * N_PROT;
    float s0 = 0.f, s1 = 0.f, s2 = 0.f, s3 = 0.f;
    for (int p = 0; p < N_PROT; p += 4) {
        s0 += xr[p + 0] * ps[(p + 0) * N_CLS + c];
        s1 += xr[p + 1] * ps[(p + 1) * N_CLS + c];
        s2 += xr[p + 2] * ps[(p + 2) * N_CLS + c];
        s3 += xr[p + 3] * ps[(p + 3) * N_CLS + c];
    }
    float s = (s0 + s1) + (s2 + s3);
    z[g][c] = s;
    __syncthreads();
    float m = z[g][0];
#pragma unroll
    for (int j = 1; j < N_CLS; j++) m = fmaxf(m, z[g][j]);
    float se = 0.f;
#pragma unroll
    for (int j = 0; j < N_CLS; j++) se += expf(z[g][j] - m);
    out[(size_t)node * N_CLS + c] = s - m - logf(se);
}

__global__ void k_out_head(const float* __restrict__ xrel, float* __restrict__ out) {
    out_head_body(xrel, out);
}
__global__ void k_out_head_scratch(float* __restrict__ out) {
    out_head_body(g_xrel_scratch, out);
}

// ---------------- launcher ----------------
extern "C" void kernel_launch(void* const* d_in, const int* in_sizes, int n_in,
                              void* d_out, int out_size) {
    const float* x    = (const float*)d_in[0];
    const int*   ei   = (const int*)d_in[1];     // int32 (JAX x64 disabled)
    const int*   prot = (const int*)d_in[2];     // int32

    // epoch may or may not be materialized as a device input; detect by size.
    int wbase = (in_sizes[3] <= 1) ? 4 : 3;
    const float* W0  = (const float*)d_in[wbase + 0];
    const float* b0  = (const float*)d_in[wbase + 1];
    const float* W1  = (const float*)d_in[wbase + 2];
    const float* b1  = (const float*)d_in[wbase + 3];
    const float* Wl1 = (const float*)d_in[wbase + 4];
    const float* bl1 = (const float*)d_in[wbase + 5];
    const float* Wl2 = (const float*)d_in[wbase + 6];
    const float* bl2 = (const float*)d_in[wbase + 7];

    const size_t SZ_OUT   = (size_t)N_NODES * N_CLS;     //   800000
    const size_t SZ_XREL  = (size_t)N_NODES * N_PROT;    // 25600000
    const size_t SZ_PROTO = (size_t)N_PROT * N_CLS;      //     8192

    float* out = (float*)d_out;                          // always [N, 16] first
    bool full = ((size_t)out_size >= SZ_OUT + SZ_XREL + SZ_PROTO);
    float* xrel = nullptr;
    float* out_proto = nullptr;
    if (full) {
        xrel      = out + SZ_OUT;
        out_proto = xrel + SZ_XREL;
    }

    const int* src = ei;
    const int* dst = ei + N_EDGES;

    // graph prep
    k_zero_counts<<<(N_NODES + 255) / 256, 256>>>();
    k_count_deg<<<(N_EDGES + 255) / 256, 256>>>(dst);
    k_dis<<<(N_NODES + 255) / 256, 256>>>();
    k_scan<<<1, 1024>>>();
    k_fill_csr<<<(N_EDGES + 255) / 256, 256>>>(src, dst);

    dim3 g1(D_HID / 64, (N_NODES + 63) / 64);
    // layer 0: xw = x @ W0 ; h = relu(aggregate + b0)
    k_gemm_xw0<<<g1, 256>>>(x, W0);
    k_aggregate<<<N_NODES, 64>>>(b0, 1);
    // layer 1: xw = h @ W1 ; h = aggregate + b1
    k_gemm_hw1<<<g1, 256>>>(W1);
    k_aggregate<<<N_NODES, 64>>>(b1, 0);

    // normalize + anchors
    k_rownorm<<<N_NODES, 64>>>();
    k_gather_anchors<<<N_PROT, 256>>>(prot);

    // prototype head
    k_proto_head<<<N_PROT, 256>>>(Wl1, bl1, Wl2, bl2, out_proto, full ? 1 : 0);

    // x_rel = hn @ anchors^T ; out = log_softmax(x_rel @ out_proto)
    dim3 g2(N_PROT / 64, (N_NODES + 63) / 64);
    if (full) {
        k_gemm_xrel<<<g2, 256>>>(xrel);
        k_out_head<<<N_NODES / 8, 128>>>(xrel, out);
    } else {
        k_gemm_xrel_scratch<<<g2, 256>>>();
        k_out_head_scratch<<<N_NODES / 8, 128>>>(out);
    }
}

// round 6
// speedup vs baseline: 1.0641x; 1.0641x over previous
#include <cuda_runtime.h>
#include <cuda_bf16.h>
#include <math.h>

#define N_NODES 50000
#define N_EDGES 800000
#define D_IN    128
#define D_HID   256
#define N_CLS   16
#define N_PROT  512

#define SCAN_TILE 1024
#define N_TILES   ((N_NODES + SCAN_TILE - 1) / SCAN_TILE)   // 49

// ---------------- scratch (device globals; no allocs allowed) ----------------
__device__ float g_dis[N_NODES];
__device__ int   g_indeg[N_NODES];
__device__ int   g_cursor[N_NODES];
__device__ int   g_rowptr[N_NODES + 1];
__device__ int   g_partial[N_TILES];
__device__ int   g_csr_src[N_EDGES];
__device__ float g_xw[(size_t)N_NODES * D_HID];       // GEMM output (pre-aggregation)
__device__ float g_h [(size_t)N_NODES * D_HID];       // hidden activations
__device__ float g_xrel_scratch[(size_t)N_NODES * N_PROT];  // fallback x_rel storage
__device__ float g_anchors [(size_t)N_PROT * D_HID];  // [P, H]
__device__ float g_anchorT [(size_t)D_HID * N_PROT];  // [H, P]
__device__ float g_outproto[(size_t)N_PROT * N_CLS];

// ---------------- f32x2 packed helpers (FFMA2 path, sm_103a) -----------------
typedef unsigned long long u64;

__device__ __forceinline__ u64 fma2(u64 a, u64 b, u64 c) {
    u64 d;
    asm("fma.rn.f32x2 %0, %1, %2, %3;" : "=l"(d) : "l"(a), "l"(b), "l"(c));
    return d;
}
__device__ __forceinline__ u64 pack2(float lo, float hi) {
    u64 d;
    asm("mov.b64 %0, {%1, %2};" : "=l"(d) : "f"(lo), "f"(hi));
    return d;
}
__device__ __forceinline__ void unpack2(u64 v, float& lo, float& hi) {
    asm("mov.b64 {%0, %1}, %2;" : "=f"(lo), "=f"(hi) : "l"(v));
}

// ---------------- graph prep ----------------
__global__ void k_zero_counts() {
    int i = blockIdx.x * blockDim.x + threadIdx.x;
    if (i < N_NODES) { g_indeg[i] = 0; g_cursor[i] = 0; }
}

// edge_index / prot are INT32 (JAX x64 disabled)
__global__ void k_count_deg(const int* __restrict__ dst) {
    int e = blockIdx.x * blockDim.x + threadIdx.x;
    if (e < N_EDGES) {
        int d = dst[e];
        if (d >= 0 && d < N_NODES) atomicAdd(&g_indeg[d], 1);
    }
}

__global__ void k_dis() {
    int i = blockIdx.x * blockDim.x + threadIdx.x;
    if (i < N_NODES) {
        float deg = (float)(g_indeg[i] + 1);  // +1 self loop
        g_dis[i] = 1.0f / sqrtf(deg);
    }
}

// ---- parallel scan: tile partial sums -> tiny serial scan -> tile rescan ----
__global__ void k_scan_partial() {
    __shared__ int sh[SCAN_TILE];
    int b = blockIdx.x, t = threadIdx.x;
    int i = b * SCAN_TILE + t;
    sh[t] = (i < N_NODES) ? g_indeg[i] : 0;
    __syncthreads();
    for (int off = SCAN_TILE / 2; off > 0; off >>= 1) {
        if (t < off) sh[t] += sh[t + off];
        __syncthreads();
    }
    if (t == 0) g_partial[b] = sh[0];
}

__global__ void k_scan_offsets() {
    // exclusive scan of N_TILES (=49) partials; trivial serial
    if (threadIdx.x == 0) {
        int acc = 0;
        for (int i = 0; i < N_TILES; i++) {
            int v = g_partial[i];
            g_partial[i] = acc;
            acc += v;
        }
    }
}

__global__ void k_scan_final() {
    __shared__ int sh[SCAN_TILE];
    int b = blockIdx.x, t = threadIdx.x;
    int i = b * SCAN_TILE + t;
    int v = (i < N_NODES) ? g_indeg[i] : 0;
    sh[t] = v;
    __syncthreads();
    // Hillis-Steele inclusive scan
    for (int off = 1; off < SCAN_TILE; off <<= 1) {
        int u = (t >= off) ? sh[t - off] : 0;
        __syncthreads();
        sh[t] += u;
        __syncthreads();
    }
    if (i < N_NODES) g_rowptr[i + 1] = sh[t] + g_partial[b];
    if (b == 0 && t == 0) g_rowptr[0] = 0;
}

__global__ void k_fill_csr(const int* __restrict__ src,
                           const int* __restrict__ dst) {
    int e = blockIdx.x * blockDim.x + threadIdx.x;
    if (e < N_EDGES) {
        int d = dst[e];
        int s = src[e];
        if (d < 0 || d >= N_NODES) return;
        int pos = atomicAdd(&g_cursor[d], 1);
        int idx = g_rowptr[d] + pos;
        if (idx >= 0 && idx < N_EDGES)
            g_csr_src[idx] = s;
    }
}

// ---------------- fp32 tiled GEMM (FFMA2): C[M,N] = A[M,K] @ B[K,N] ----------
// 64x64 tile, 256 threads, microtile 4 rows x 4 cols held as 2 row-pairs of f32x2
__device__ __forceinline__ void gemm_body(const float* __restrict__ A,
                                          const float* __restrict__ B,
                                          float* __restrict__ C,
                                          int M, int N, int K) {
    __shared__ float As[16][64];   // [k][m] — rows contiguous => packed pair loads
    __shared__ float Bs[16][64];   // [k][n]
    int bm = blockIdx.y * 64;
    int bn = blockIdx.x * 64;
    int t = threadIdx.x;
    int tx = t % 16, ty = t / 16;

    u64 acc2[2][4];                // [row-pair][col]; each holds rows (2r2, 2r2+1)
#pragma unroll
    for (int r = 0; r < 2; r++)
#pragma unroll
        for (int c = 0; c < 4; c++) acc2[r][c] = pack2(0.f, 0.f);

    for (int k0 = 0; k0 < K; k0 += 16) {
        {   // load A tile (64 rows x 16 cols)
            int m = t >> 2;
            int kq = t & 3;
            float4 v = make_float4(0.f, 0.f, 0.f, 0.f);
            if (bm + m < M)
                v = *(const float4*)&A[(size_t)(bm + m) * K + k0 + kq * 4];
            As[kq * 4 + 0][m] = v.x;
            As[kq * 4 + 1][m] = v.y;
            As[kq * 4 + 2][m] = v.z;
            As[kq * 4 + 3][m] = v.w;
        }
        {   // load B tile (16 rows x 64 cols)
            int kk = t >> 4;
            int nq = t & 15;
            float4 v = *(const float4*)&B[(size_t)(k0 + kk) * N + bn + nq * 4];
            Bs[kk][nq * 4 + 0] = v.x;
            Bs[kk][nq * 4 + 1] = v.y;
            Bs[kk][nq * 4 + 2] = v.z;
            Bs[kk][nq * 4 + 3] = v.w;
        }
        __syncthreads();
#pragma unroll
        for (int kk = 0; kk < 16; kk++) {
            // A row-pairs come out of smem already packed (8B aligned: ty*4 even)
            u64 a0 = *(const u64*)&As[kk][ty * 4 + 0];
            u64 a1 = *(const u64*)&As[kk][ty * 4 + 2];
            float b0 = Bs[kk][tx * 4 + 0];
            float b1 = Bs[kk][tx * 4 + 1];
            float b2 = Bs[kk][tx * 4 + 2];
            float b3 = Bs[kk][tx * 4 + 3];
            u64 bb0 = pack2(b0, b0), bb1 = pack2(b1, b1);
            u64 bb2 = pack2(b2, b2), bb3 = pack2(b3, b3);
            acc2[0][0] = fma2(a0, bb0, acc2[0][0]);
            acc2[0][1] = fma2(a0, bb1, acc2[0][1]);
            acc2[0][2] = fma2(a0, bb2, acc2[0][2]);
            acc2[0][3] = fma2(a0, bb3, acc2[0][3]);
            acc2[1][0] = fma2(a1, bb0, acc2[1][0]);
            acc2[1][1] = fma2(a1, bb1, acc2[1][1]);
            acc2[1][2] = fma2(a1, bb2, acc2[1][2]);
            acc2[1][3] = fma2(a1, bb3, acc2[1][3]);
        }
        __syncthreads();
    }
    // writeout: unpack row-pairs
#pragma unroll
    for (int r2 = 0; r2 < 2; r2++) {
        float lo0, hi0, lo1, hi1, lo2, hi2, lo3, hi3;
        unpack2(acc2[r2][0], lo0, hi0);
        unpack2(acc2[r2][1], lo1, hi1);
        unpack2(acc2[r2][2], lo2, hi2);
        unpack2(acc2[r2][3], lo3, hi3);
        int m0 = bm + ty * 4 + r2 * 2;
        if (m0 < M)
            *(float4*)&C[(size_t)m0 * N + bn + tx * 4] = make_float4(lo0, lo1, lo2, lo3);
        if (m0 + 1 < M)
            *(float4*)&C[(size_t)(m0 + 1) * N + bn + tx * 4] = make_float4(hi0, hi1, hi2, hi3);
    }
}

// bindings
__global__ void k_gemm_xw0(const float* __restrict__ x, const float* __restrict__ W0) {
    gemm_body(x, W0, g_xw, N_NODES, D_HID, D_IN);
}
__global__ void k_gemm_hw1(const float* __restrict__ W1) {
    gemm_body(g_h, W1, g_xw, N_NODES, D_HID, D_HID);
}
__global__ void k_gemm_xrel(float* __restrict__ xrel) {
    gemm_body(g_h, g_anchorT, xrel, N_NODES, N_PROT, D_HID);
}
__global__ void k_gemm_xrel_scratch() {
    gemm_body(g_h, g_anchorT, g_xrel_scratch, N_NODES, N_PROT, D_HID);
}

// ---------------- GCN aggregation (CSR gather, deterministic writes) ---------
__global__ void k_aggregate(const float* __restrict__ bias, int do_relu) {
    int node = blockIdx.x;
    int t = threadIdx.x;  // 64 threads, float4 each -> 256 cols
    float din = g_dis[node];
    int beg = g_rowptr[node], end = g_rowptr[node + 1];
    const float4* xw4 = (const float4*)g_xw;
    float4 acc = make_float4(0.f, 0.f, 0.f, 0.f);
    for (int e = beg; e < end; e++) {
        int s = g_csr_src[e];
        float w = g_dis[s] * din;
        float4 v = xw4[(size_t)s * 64 + t];
        acc.x += w * v.x; acc.y += w * v.y; acc.z += w * v.z; acc.w += w * v.w;
    }
    { // self loop
        float w = din * din;
        float4 v = xw4[(size_t)node * 64 + t];
        acc.x += w * v.x; acc.y += w * v.y; acc.z += w * v.z; acc.w += w * v.w;
    }
    float4 bv = ((const float4*)bias)[t];
    acc.x += bv.x; acc.y += bv.y; acc.z += bv.z; acc.w += bv.w;
    if (do_relu) {
        acc.x = fmaxf(acc.x, 0.f); acc.y = fmaxf(acc.y, 0.f);
        acc.z = fmaxf(acc.z, 0.f); acc.w = fmaxf(acc.w, 0.f);
    }
    ((float4*)g_h)[(size_t)node * 64 + t] = acc;
}

// ---------------- L2 row-normalize g_h in place ------------------------------
__global__ void k_rownorm() {
    int node = blockIdx.x;
    int t = threadIdx.x;  // 64
    float4* row = (float4*)(g_h + (size_t)node * D_HID);
    float4 v = row[t];
    float s = v.x * v.x + v.y * v.y + v.z * v.z + v.w * v.w;
#pragma unroll
    for (int off = 16; off >= 1; off >>= 1)
        s += __shfl_xor_sync(0xFFFFFFFFu, s, off);
    __shared__ float ws[2];
    if ((t & 31) == 0) ws[t >> 5] = s;
    __syncthreads();
    s = ws[0] + ws[1];
    float r = 1.0f / sqrtf(s);
    v.x *= r; v.y *= r; v.z *= r; v.w *= r;
    row[t] = v;
}

// ---------------- anchor gather (rows + transposed) --------------------------
__global__ void k_gather_anchors(const int* __restrict__ prot) {
    int p = blockIdx.x;
    int t = threadIdx.x;  // 256
    int nl = prot[p];
    int node = (nl >= 0 && nl < N_NODES) ? nl : 0;
    float v = g_h[(size_t)node * D_HID + t];
    g_anchors[(size_t)p * D_HID + t] = v;
    g_anchorT[(size_t)t * N_PROT + p] = v;
}

// ---------------- prototype head: log_softmax(lin(anchors)) ------------------
__global__ void k_proto_head(const float* __restrict__ Wl1, const float* __restrict__ bl1,
                             const float* __restrict__ Wl2, const float* __restrict__ bl2,
                             float* __restrict__ out_proto_dst, int write_out) {
    int p = blockIdx.x;
    int t = threadIdx.x;  // 256
    __shared__ float a[D_HID];
    __shared__ float h1[D_HID];
    __shared__ float z[N_CLS];
    a[t] = g_anchors[(size_t)p * D_HID + t];
    __syncthreads();
    float s = bl1[t];
#pragma unroll 4
    for (int k = 0; k < D_HID; k++) s += a[k] * Wl1[(size_t)k * D_HID + t];
    h1[t] = fmaxf(s, 0.0f);
    __syncthreads();
    if (t < N_CLS) {
        float s2 = bl2[t];
#pragma unroll 4
        for (int k = 0; k < D_HID; k++) s2 += h1[k] * Wl2[(size_t)k * N_CLS + t];
        z[t] = s2;
    }
    __syncthreads();
    if (t < N_CLS) {
        float m = z[0];
#pragma unroll
        for (int j = 1; j < N_CLS; j++) m = fmaxf(m, z[j]);
        float se = 0.f;
#pragma unroll
        for (int j = 0; j < N_CLS; j++) se += expf(z[j] - m);
        float v = z[t] - m - logf(se);
        g_outproto[(size_t)p * N_CLS + t] = v;
        if (write_out) out_proto_dst[(size_t)p * N_CLS + t] = v;
    }
}

// ---------------- out = log_softmax(x_rel @ out_proto) -----------------------
__device__ __forceinline__ void out_head_body(const float* __restrict__ xr_base,
                                              float* __restrict__ out) {
    __shared__ float ps[N_PROT * N_CLS];  // 32KB
    __shared__ float z[8][N_CLS];
    int t = threadIdx.x;
    for (int i = t; i < N_PROT * N_CLS; i += 128) ps[i] = g_outproto[i];
    __syncthreads();
    int g = t >> 4;          // node within block
    int c = t & 15;          // class
    int node = blockIdx.x * 8 + g;
    const float* xr = xr_base + (size_t)node * N_PROT;
    float s0 = 0.f, s1 = 0.f, s2 = 0.f, s3 = 0.f;
    for (int p = 0; p < N_PROT; p += 4) {
        s0 += xr[p + 0] * ps[(p + 0) * N_CLS + c];
        s1 += xr[p + 1] * ps[(p + 1) * N_CLS + c];
        s2 += xr[p + 2] * ps[(p + 2) * N_CLS + c];
        s3 += xr[p + 3] * ps[(p + 3) * N_CLS + c];
    }
    float s = (s0 + s1) + (s2 + s3);
    z[g][c] = s;
    __syncthreads();
    float m = z[g][0];
#pragma unroll
    for (int j = 1; j < N_CLS; j++) m = fmaxf(m, z[g][j]);
    float se = 0.f;
#pragma unroll
    for (int j = 0; j < N_CLS; j++) se += expf(z[g][j] - m);
    out[(size_t)node * N_CLS + c] = s - m - logf(se);
}

__global__ void k_out_head(const float* __restrict__ xrel, float* __restrict__ out) {
    out_head_body(xrel, out);
}
__global__ void k_out_head_scratch(float* __restrict__ out) {
    out_head_body(g_xrel_scratch, out);
}

// ---------------- launcher ----------------
extern "C" void kernel_launch(void* const* d_in, const int* in_sizes, int n_in,
                              void* d_out, int out_size) {
    const float* x    = (const float*)d_in[0];
    const int*   ei   = (const int*)d_in[1];     // int32
    const int*   prot = (const int*)d_in[2];     // int32

    int wbase = (in_sizes[3] <= 1) ? 4 : 3;
    const float* W0  = (const float*)d_in[wbase + 0];
    const float* b0  = (const float*)d_in[wbase + 1];
    const float* W1  = (const float*)d_in[wbase + 2];
    const float* b1  = (const float*)d_in[wbase + 3];
    const float* Wl1 = (const float*)d_in[wbase + 4];
    const float* bl1 = (const float*)d_in[wbase + 5];
    const float* Wl2 = (const float*)d_in[wbase + 6];
    const float* bl2 = (const float*)d_in[wbase + 7];

    const size_t SZ_OUT   = (size_t)N_NODES * N_CLS;
    const size_t SZ_XREL  = (size_t)N_NODES * N_PROT;
    const size_t SZ_PROTO = (size_t)N_PROT * N_CLS;

    float* out = (float*)d_out;
    bool full = ((size_t)out_size >= SZ_OUT + SZ_XREL + SZ_PROTO);
    float* xrel = nullptr;
    float* out_proto = nullptr;
    if (full) {
        xrel      = out + SZ_OUT;
        out_proto = xrel + SZ_XREL;
    }

    const int* src = ei;
    const int* dst = ei + N_EDGES;

    // graph prep
    k_zero_counts<<<(N_NODES + 255) / 256, 256>>>();
    k_count_deg<<<(N_EDGES + 255) / 256, 256>>>(dst);
    k_dis<<<(N_NODES + 255) / 256, 256>>>();
    k_scan_partial<<<N_TILES, SCAN_TILE>>>();
    k_scan_offsets<<<1, 32>>>();
    k_scan_final<<<N_TILES, SCAN_TILE>>>();
    k_fill_csr<<<(N_EDGES + 255) / 256, 256>>>(src, dst);

    dim3 g1(D_HID / 64, (N_NODES + 63) / 64);
    k_gemm_xw0<<<g1, 256>>>(x, W0);
    k_aggregate<<<N_NODES, 64>>>(b0, 1);
    k_gemm_hw1<<<g1, 256>>>(W1);
    k_aggregate<<<N_NODES, 64>>>(b1, 0);

    k_rownorm<<<N_NODES, 64>>>();
    k_gather_anchors<<<N_PROT, 256>>>(prot);

    k_proto_head<<<N_PROT, 256>>>(Wl1, bl1, Wl2, bl2, out_proto, full ? 1 : 0);

    dim3 g2(N_PROT / 64, (N_NODES + 63) / 64);
    if (full) {
        k_gemm_xrel<<<g2, 256>>>(xrel);
        k_out_head<<<N_NODES / 8, 128>>>(xrel, out);
    } else {
        k_gemm_xrel_scratch<<<g2, 256>>>();
        k_out_head_scratch<<<N_NODES / 8, 128>>>(out);
    }
}